// round 13
// baseline (speedup 1.0000x reference)
#include <cuda_runtime.h>
#include <cstdint>

#define THREADS 192
#define NCH 12              // 768 / 64 floats per chunk
#define NP1 1369
#define RS 72               // row stride (72 mod 32 = 8 -> conflict-free pairs)
#define ASTG (48*RS)        // 3456
#define BSTG (40*RS)        // 2880

// ---- smem float offsets ----
#define AOF 0               // A stages: 2 * 3456
#define BOF 6912            // B stages: 2 * 2880 -> ends 12672
#define GWF 12672           // g*w vector 768 -> 13440
#define WPF 13440           // 6 warp sbw partials (+pad) -> 13448
#define STF 13448           // sxx per row, 72 -> 13520
#define SXF 13520           // row sums 72 -> 13592
#define SXGF 13592          // row (x.gw) 72 -> 13664
#define RNF 13664           // rsqrt norms 72 -> 13736
#define DUF 13736           // dustbin*10 72 -> 13808
#define UF  13808
#define VF  13845
#define EUF 13882
#define EVF 13919
#define TOTF 13956
#define SGWS 13957
#define SM_FLOATS 13960
#define SM_BYTES (SM_FLOATS*4)   // 55840 -> 4 CTAs/SM
// post-loop aliases (A stages dead after main loop)
#define CSF 0               // couplings 1369 (A stage 0)
#define ECF 3456            // exp couplings 1369 (A stage 1)

#define NORMC (-4.27666611901605529f)   // -log(72)
#define LMD   (-0.69314718055994531f)   // log(36)-log(72)

__device__ __forceinline__ void fma2(unsigned long long &d,
                                     unsigned long long a,
                                     unsigned long long b) {
    asm volatile("fma.rn.f32x2 %0, %1, %2, %0;" : "+l"(d) : "l"(a), "l"(b));
}
__device__ __forceinline__ float lo32(unsigned long long a){ return __uint_as_float((unsigned)a); }
__device__ __forceinline__ float hi32(unsigned long long a){ return __uint_as_float((unsigned)(a>>32)); }

__device__ __forceinline__ uint32_t f2tf(float f) {
    uint32_t u; asm("cvt.rna.tf32.f32 %0, %1;" : "=r"(u) : "f"(f)); return u;
}
__device__ __forceinline__ void mma1688(float* d, const uint32_t* a, const uint32_t* b) {
    asm volatile(
        "mma.sync.aligned.m16n8k8.row.col.f32.tf32.tf32.f32 "
        "{%0,%1,%2,%3}, {%4,%5,%6,%7}, {%8,%9}, {%0,%1,%2,%3};"
        : "+f"(d[0]), "+f"(d[1]), "+f"(d[2]), "+f"(d[3])
        : "r"(a[0]), "r"(a[1]), "r"(a[2]), "r"(a[3]), "r"(b[0]), "r"(b[1]));
}
__device__ __forceinline__ void cp16(uint32_t dst, const float* src) {
    asm volatile("cp.async.cg.shared.global [%0], [%1], 16;"
                 :: "r"(dst), "l"(src) : "memory");
}

// one 72-row x 64-float chunk: x rows -> A stage rows 0-35, y rows -> B rows 0-35
__device__ __forceinline__ void load_chunk(uint32_t smb, const float* xb,
                                           const float* yb, int c, int t) {
    uint32_t sA = smb + AOF*4 + (c&1)*(ASTG*4);
    uint32_t sB = smb + BOF*4 + (c&1)*(BSTG*4);
    #pragma unroll
    for (int r = 0; r < 6; ++r) {
        int op = t + THREADS*r;          // 0..1151 exact
        int row = op >> 4, c4 = op & 15;
        if (row < 36)
            cp16(sA + row*(RS*4) + c4*16, xb + row*768 + c*64 + c4*4);
        else
            cp16(sB + (row-36)*(RS*4) + c4*16, yb + (row-36)*768 + c*64 + c4*4);
    }
    asm volatile("cp.async.commit_group;" ::: "memory");
}

// ======================= fused kernel ===================================
__global__ void __launch_bounds__(THREADS, 4)
k_fused(const float* __restrict__ X, const float* __restrict__ Y,
        const float* __restrict__ G, const float* __restrict__ Bln,
        const float* __restrict__ W, const float* __restrict__ Blin,
        float* __restrict__ out, int B)
{
    extern __shared__ __align__(16) float smf[];
    uint32_t smb;
    asm("{ .reg .u64 tt; cvta.to.shared.u64 tt, %1; cvt.u32.u64 %0, tt; }"
        : "=r"(smb) : "l"(smf));
    const int t = threadIdx.x;
    const int w = t >> 5, lid = t & 31;
    const int g = lid >> 2, tig = lid & 3;
    const int b = blockIdx.x;
    const float* xb = X + (size_t)b * 27648;
    const float* yb = Y + (size_t)b * 27648;

    // init special rows, both stages: row 36 = gw (filled per chunk), 37 = ones,
    // 38+ = zeros. (ones row -> MMA computes row/col sums)
    for (int i = t; i < 2*14*64; i += THREADS) {
        int st = i / 896; int rem = i - st*896;
        int r = rem >> 6, col = rem & 63;
        float val = (r == 0 || r == 11) ? 1.f : 0.f;
        if (r < 11) smf[AOF + st*ASTG + (37+r)*RS + col] = val;
        else        smf[BOF + st*BSTG + (37+r-11)*RS + col] = val;
    }

    // prefetch chunk 0
    load_chunk(smb, xb, yb, 0, t);

    // g*w vector + per-warp sbw partial (768 = 4*192 exact)
    {
        float sbw = 0.f;
        float gv0 = 0.f;
        #pragma unroll
        for (int r = 0; r < 4; ++r) {
            int h = t + THREADS*r;
            float wv = W[h];
            float gv = G[h]*wv;
            smf[GWF + h] = gv;
            if (r == 0) gv0 = gv;
            sbw += Bln[h]*wv;
        }
        #pragma unroll
        for (int o = 16; o > 0; o >>= 1)
            sbw += __shfl_down_sync(0xffffffffu, sbw, o);
        if (lid == 0) smf[WPF + w] = sbw;
        if (t < 64) {
            smf[AOF + 36*RS + t] = gv0;
            smf[BOF + 36*RS + t] = gv0;
        }
    }

    // GEMM: all 6 warps.  warp = (mt = w>>1, nhalf = w&1)
    const int mt  = w >> 1;
    const int nh  = w & 1;
    const int nt0 = nh ? 3 : 0;
    const int ntn = nh ? 2 : 3;
    // B-stats tile ownership: (1,*)->j0, (2,*)->j1, (0,0)->j2, (0,1)->none
    const int jb = (mt == 1) ? 0 : (mt == 2) ? 1 : (nh == 0 ? 2 : -1);
    float acc[3][4];
    #pragma unroll
    for (int j = 0; j < 3; ++j)
        #pragma unroll
        for (int e = 0; e < 4; ++e) acc[j][e] = 0.f;

    // fragment-harvested sum-of-squares accumulators (raw fp32, f32x2 lanes)
    unsigned long long sxA0 = 0ULL, sxA1 = 0ULL, sxB = 0ULL;

    #pragma unroll 1
    for (int c = 0; c < NCH; ++c) {
        asm volatile("cp.async.wait_group 0;" ::: "memory");
        __syncthreads();
        if (c + 1 < NCH) {
            load_chunk(smb, xb, yb, c+1, t);
            if (t < 64) {   // gw row for chunk c+1 (other buffer)
                float gv = smf[GWF + (c+1)*64 + t];
                int s2 = (c+1)&1;
                smf[AOF + s2*ASTG + 36*RS + t] = gv;
                smf[BOF + s2*BSTG + 36*RS + t] = gv;
            }
        }

        // ---- tensor-core GEMM; k-paired LDS.64 fragments + sxx harvest ----
        {
            const float* As = smf + AOF + (c&1)*ASTG + (mt*16 + g)*RS + 2*tig;
            const float* Bs = smf + BOF + (c&1)*BSTG + (nt0*8 + g)*RS + 2*tig;
            #pragma unroll
            for (int ks = 0; ks < 8; ++ks) {
                const int ko = ks*8;
                unsigned long long aLoU =
                    *reinterpret_cast<const unsigned long long*>(As + ko);
                unsigned long long aHiU =
                    *reinterpret_cast<const unsigned long long*>(As + 8*RS + ko);
                if (nh == 0) {             // A-row sxx (dedup: one warp per mt)
                    fma2(sxA0, aLoU, aLoU);
                    fma2(sxA1, aHiU, aHiU);
                }
                uint32_t a[4];
                a[0] = f2tf(lo32(aLoU));
                a[1] = f2tf(lo32(aHiU));
                a[2] = f2tf(hi32(aLoU));
                a[3] = f2tf(hi32(aHiU));
                #pragma unroll
                for (int j = 0; j < 3; ++j) {
                    if (j < ntn) {
                        unsigned long long bbU =
                            *reinterpret_cast<const unsigned long long*>(
                                Bs + j*8*RS + ko);
                        if (j == jb) fma2(sxB, bbU, bbU);   // B-row sxx
                        uint32_t bf[2];
                        bf[0] = f2tf(lo32(bbU));
                        bf[1] = f2tf(hi32(bbU));
                        mma1688(acc[j], a, bf);
                    }
                }
            }
        }
    }

    // ---- reduce harvested sxx across the 4 tig lanes, write per-row ----
    if (nh == 0) {
        float s0 = lo32(sxA0) + hi32(sxA0);
        float s1 = lo32(sxA1) + hi32(sxA1);
        s0 += __shfl_down_sync(0xffffffffu, s0, 2, 4);
        s0 += __shfl_down_sync(0xffffffffu, s0, 1, 4);
        s1 += __shfl_down_sync(0xffffffffu, s1, 2, 4);
        s1 += __shfl_down_sync(0xffffffffu, s1, 1, 4);
        if (tig == 0) {
            int r = mt*16 + g;
            if (r < 36)     smf[STF + r] = s0;
            if (r + 8 < 36) smf[STF + r + 8] = s1;
        }
    }
    if (jb >= 0) {
        float sb = lo32(sxB) + hi32(sxB);
        sb += __shfl_down_sync(0xffffffffu, sb, 2, 4);
        sb += __shfl_down_sync(0xffffffffu, sb, 1, 4);
        if (tig == 0) {
            int r = (nh ? 24 : 0) + jb*8 + g;
            if (r < 36) smf[STF + 36 + r] = sb;
        }
    }

    // ---- extract MMA-computed stats: col36 = x.gw, col37 = sum(x),
    //      row36 = gw.y, row37 = sum(y), (36,37) = sum(gw) ----
    #pragma unroll
    for (int j = 0; j < 3; ++j) {
        if (j < ntn) {
            int r0 = mt*16 + g;
            int c0 = (nt0 + j)*8 + 2*tig;
            #pragma unroll
            for (int e = 0; e < 4; ++e) {
                int rr = r0 + (e >> 1)*8;
                int cc = c0 + (e & 1);
                float val = acc[j][e];
                if (rr < 36) {
                    if (cc == 36)      smf[SXGF + rr] = val;
                    else if (cc == 37) smf[SXF + rr] = val;
                } else if (rr == 36) {
                    if (cc < 36)       smf[SXGF + 36 + cc] = val;
                    else if (cc == 37) smf[SGWS] = val;
                } else if (rr == 37 && cc < 36) {
                    smf[SXF + 36 + cc] = val;
                }
            }
        }
    }
    __syncthreads();    // main loop done; stage buffers dead -> aliases live

    // per-row finalize (72 rows)
    if (t < 72) {
        float Sxx = smf[STF + t];
        float Sx  = smf[SXF + t];
        float Sxg = smf[SXGF + t];
        float Sgw = smf[SGWS];
        float Sbw = 0.f;
        #pragma unroll
        for (int j = 0; j < 6; ++j) Sbw += smf[WPF + j];
        smf[RNF + t] = rsqrtf(Sxx);
        float mu  = Sx * (1.f/768.f);
        float var = Sxx * (1.f/768.f) - mu*mu;
        float rsd = rsqrtf(var + 1e-5f);
        smf[DUF + t] = tanhf((Sxg - mu*Sgw)*rsd + Sbw + Blin[0]) * 10.f;
    }
    if (t < 37) {
        smf[UF + t] = 0.f; smf[VF + t] = 0.f;
        smf[EUF + t] = 1.f; smf[EVF + t] = 1.f;
    }
    if (t == 0) smf[TOTF] = 0.f;
    __syncthreads();

    // write scaled couplings from MMA accumulators
    #pragma unroll
    for (int j = 0; j < 3; ++j) {
        if (j < ntn) {
            int r0 = mt*16 + g;
            int c0 = (nt0 + j)*8 + 2*tig;
            #pragma unroll
            for (int e = 0; e < 4; ++e) {
                int rr = r0 + (e >> 1)*8;
                int cc = c0 + (e & 1);
                if (rr < 36 && cc < 36)
                    smf[CSF + rr*37 + cc] =
                        acc[j][e] * smf[RNF+rr] * smf[RNF+36+cc] * 10.f;
            }
        }
    }
    if (t < 36) {
        smf[CSF + t*37 + 36] = smf[DUF + t];
        smf[CSF + 36*37 + t] = smf[DUF + 36 + t];
    }
    if (t == 0) smf[CSF + 36*37 + 36] = -1000.f;
    __syncthreads();

    for (int i = t; i < NP1; i += THREADS) smf[ECF + i] = __expf(smf[CSF + i]);
    __syncthreads();

    // ---- Sinkhorn: warps 0-1 only, named barrier ----
    if (t < 64) {
        const int m = t;
        const bool act = t < 37;
        const float lr = (m < 36) ? NORMC : LMD;
        #pragma unroll 1
        for (int it = 0; it < 20; ++it) {
            if (act) {
                const float* er = smf + ECF + m*37;
                float s0=0.f, s1=0.f, s2=0.f, s3=0.f;
                #pragma unroll
                for (int n = 0; n < 36; n += 4) {
                    s0 = fmaf(er[n+0], smf[EVF+n+0], s0);
                    s1 = fmaf(er[n+1], smf[EVF+n+1], s1);
                    s2 = fmaf(er[n+2], smf[EVF+n+2], s2);
                    s3 = fmaf(er[n+3], smf[EVF+n+3], s3);
                }
                s0 = fmaf(er[36], smf[EVF+36], s0);
                float uu = lr - __logf((s0+s1)+(s2+s3));
                smf[UF + m] = uu;
                smf[EUF + m] = __expf(uu);
            }
            asm volatile("bar.sync 5, 64;" ::: "memory");
            if (act) {
                const float* ecc = smf + ECF + m;
                float s0=0.f, s1=0.f, s2=0.f, s3=0.f;
                #pragma unroll
                for (int n = 0; n < 36; n += 4) {
                    s0 = fmaf(ecc[(n+0)*37], smf[EUF+n+0], s0);
                    s1 = fmaf(ecc[(n+1)*37], smf[EUF+n+1], s1);
                    s2 = fmaf(ecc[(n+2)*37], smf[EUF+n+2], s2);
                    s3 = fmaf(ecc[(n+3)*37], smf[EUF+n+3], s3);
                }
                s0 = fmaf(ecc[36*37], smf[EUF+36], s0);
                float vv = lr - __logf((s0+s1)+(s2+s3));
                smf[VF + m] = vv;
                smf[EVF + m] = __expf(vv);
            }
            asm volatile("bar.sync 5, 64;" ::: "memory");
        }
    }
    __syncthreads();

    // ---- epilogue: Z + total;  exp(Z) = 72 * ec * eu * ev ----
    float* ob = out + (size_t)b * NP1;
    float part = 0.f;
    for (int i = t; i < NP1; i += THREADS) {
        int mm = i / 37;
        int nn = i - mm*37;
        float cc = smf[CSF + i];
        ob[i] = cc + smf[UF + mm] + smf[VF + nn] - NORMC;
        if (mm < 36 && nn < 36)
            part += smf[ECF + i] * smf[EUF + mm] * smf[EVF + nn] * cc;
    }
    #pragma unroll
    for (int o = 16; o > 0; o >>= 1)
        part += __shfl_down_sync(0xffffffffu, part, o);
    if (lid == 0) atomicAdd(&smf[TOTF], part * 72.f);
    __syncthreads();
    if (t == 0) out[(size_t)B*NP1 + b] = smf[TOTF];
}

// ======================= launch =========================================
extern "C" void kernel_launch(void* const* d_in, const int* in_sizes, int n_in,
                              void* d_out, int out_size)
{
    const float* x  = (const float*)d_in[0];
    const float* y  = (const float*)d_in[1];
    const float* g  = (const float*)d_in[2];
    const float* bb = (const float*)d_in[3];
    const float* w  = (const float*)d_in[4];
    const float* bl = (const float*)d_in[5];
    const int B = in_sizes[0] / (36 * 768);
    float* out = (float*)d_out;

    cudaFuncSetAttribute(k_fused,
                         cudaFuncAttributeMaxDynamicSharedMemorySize, SM_BYTES);
    k_fused<<<B, THREADS, SM_BYTES>>>(x, y, g, bb, w, bl, out, B);
}

// round 14
// speedup vs baseline: 1.1326x; 1.1326x over previous
#include <cuda_runtime.h>
#include <cstdint>

#define THREADS 192
#define NCH 12              // 768 / 64 floats per chunk
#define NP1 1369
#define RS 72               // row stride (72 mod 32 = 8 -> conflict-free pairs)
#define ASTG (48*RS)        // 3456
#define BSTG (40*RS)        // 2880

// ---- smem float offsets ----
#define AOF 0               // A stages: 2 * 3456
#define BOF 6912            // B stages: 2 * 2880 -> ends 12672
#define GWF 12672           // g*w vector 768 -> 13440
#define WPF 13440           // 6 warp sbw partials (+pad) -> 13448
#define STF 13448           // sxx per row-half, 144 -> 13592
#define SXF 13592           // row sums 72 -> 13664
#define SXGF 13664          // row (x.gw) 72 -> 13736
#define RNF 13736           // rsqrt norms 72 -> 13808
#define DUF 13808           // dustbin*10 72 -> 13880
#define UF  13880
#define VF  13917
#define EUF 13954
#define EVF 13991
#define TOTF 14028
#define SGWS 14029
#define SM_FLOATS 14032
#define SM_BYTES (SM_FLOATS*4)   // 56128 -> 4 CTAs/SM
// post-loop aliases (A stages dead after main loop)
#define CSF 0               // couplings 1369 (A stage 0)
#define ECF 3456            // exp couplings 1369 (A stage 1)
// acc-exchange scratch (B stage 0, dead after main loop): 3*672 = 2016 floats
#define XCF BOF

#define NORMC (-4.27666611901605529f)   // -log(72)
#define LMD   (-0.69314718055994531f)   // log(36)-log(72)

__device__ __forceinline__ void fma2(unsigned long long &d,
                                     unsigned long long a,
                                     unsigned long long b) {
    asm volatile("fma.rn.f32x2 %0, %1, %2, %0;" : "+l"(d) : "l"(a), "l"(b));
}
__device__ __forceinline__ float lo32(unsigned long long a){ return __uint_as_float((unsigned)a); }
__device__ __forceinline__ float hi32(unsigned long long a){ return __uint_as_float((unsigned)(a>>32)); }

__device__ __forceinline__ uint32_t f2tf(float f) {
    uint32_t u; asm("cvt.rna.tf32.f32 %0, %1;" : "=r"(u) : "f"(f)); return u;
}
__device__ __forceinline__ void mma1688(float* d, const uint32_t* a, const uint32_t* b) {
    asm volatile(
        "mma.sync.aligned.m16n8k8.row.col.f32.tf32.tf32.f32 "
        "{%0,%1,%2,%3}, {%4,%5,%6,%7}, {%8,%9}, {%0,%1,%2,%3};"
        : "+f"(d[0]), "+f"(d[1]), "+f"(d[2]), "+f"(d[3])
        : "r"(a[0]), "r"(a[1]), "r"(a[2]), "r"(a[3]), "r"(b[0]), "r"(b[1]));
}
__device__ __forceinline__ void cp16(uint32_t dst, const float* src) {
    asm volatile("cp.async.cg.shared.global [%0], [%1], 16;"
                 :: "r"(dst), "l"(src) : "memory");
}

// one 72-row x 64-float chunk: x rows -> A stage rows 0-35, y rows -> B rows 0-35
__device__ __forceinline__ void load_chunk(uint32_t smb, const float* xb,
                                           const float* yb, int c, int t) {
    uint32_t sA = smb + AOF*4 + (c&1)*(ASTG*4);
    uint32_t sB = smb + BOF*4 + (c&1)*(BSTG*4);
    #pragma unroll
    for (int r = 0; r < 6; ++r) {
        int op = t + THREADS*r;          // 0..1151 exact
        int row = op >> 4, c4 = op & 15;
        if (row < 36)
            cp16(sA + row*(RS*4) + c4*16, xb + row*768 + c*64 + c4*4);
        else
            cp16(sB + (row-36)*(RS*4) + c4*16, yb + (row-36)*768 + c*64 + c4*4);
    }
    asm volatile("cp.async.commit_group;" ::: "memory");
}

// ======================= fused kernel ===================================
__global__ void __launch_bounds__(THREADS, 4)
k_fused(const float* __restrict__ X, const float* __restrict__ Y,
        const float* __restrict__ G, const float* __restrict__ Bln,
        const float* __restrict__ W, const float* __restrict__ Blin,
        float* __restrict__ out, int B)
{
    extern __shared__ __align__(16) float smf[];
    uint32_t smb;
    asm("{ .reg .u64 tt; cvta.to.shared.u64 tt, %1; cvt.u32.u64 %0, tt; }"
        : "=r"(smb) : "l"(smf));
    const int t = threadIdx.x;
    const int w = t >> 5, lid = t & 31;
    const int g = lid >> 2, tig = lid & 3;
    const int b = blockIdx.x;
    const float* xb = X + (size_t)b * 27648;
    const float* yb = Y + (size_t)b * 27648;

    // init special rows, both stages: row 36 = gw (per chunk), 37 = ones, 38+ = 0
    for (int i = t; i < 2*14*64; i += THREADS) {
        int st = i / 896; int rem = i - st*896;
        int r = rem >> 6, col = rem & 63;
        float val = (r == 0 || r == 11) ? 1.f : 0.f;
        if (r < 11) smf[AOF + st*ASTG + (37+r)*RS + col] = val;
        else        smf[BOF + st*BSTG + (37+r-11)*RS + col] = val;
    }

    // prefetch chunk 0
    load_chunk(smb, xb, yb, 0, t);

    // g*w vector + per-warp sbw partial (768 = 4*192 exact)
    {
        float sbw = 0.f;
        float gv0 = 0.f;
        #pragma unroll
        for (int r = 0; r < 4; ++r) {
            int h = t + THREADS*r;
            float wv = W[h];
            float gv = G[h]*wv;
            smf[GWF + h] = gv;
            if (r == 0) gv0 = gv;
            sbw += Bln[h]*wv;
        }
        #pragma unroll
        for (int o = 16; o > 0; o >>= 1)
            sbw += __shfl_down_sync(0xffffffffu, sbw, o);
        if (lid == 0) smf[WPF + w] = sbw;
        if (t < 64) {
            smf[AOF + 36*RS + t] = gv0;
            smf[BOF + 36*RS + t] = gv0;
        }
    }

    // GEMM: warp = (mt = w>>1, kh = w&1).  Each warp: 16 rows x ALL 5 n-tiles,
    // half the k-range.  Partials merged after the loop.
    const int mt = w >> 1;
    const int kh = w & 1;
    float acc[5][4];
    #pragma unroll
    for (int j = 0; j < 5; ++j)
        #pragma unroll
        for (int e = 0; e < 4; ++e) acc[j][e] = 0.f;

    // stats: sxx only, one half-row per thread for t<144
    unsigned long long sxx2 = 0ULL;
    const int srow = t >> 1, shalf = t & 1;

    #pragma unroll 1
    for (int c = 0; c < NCH; ++c) {
        asm volatile("cp.async.wait_group 0;" ::: "memory");
        __syncthreads();
        if (c + 1 < NCH) {
            load_chunk(smb, xb, yb, c+1, t);
            if (t < 64) {   // gw row for chunk c+1 (other buffer)
                float gv = smf[GWF + (c+1)*64 + t];
                int s2 = (c+1)&1;
                smf[AOF + s2*ASTG + 36*RS + t] = gv;
                smf[BOF + s2*BSTG + 36*RS + t] = gv;
            }
        }

        // ---- tensor-core GEMM; k-split halves, k-paired LDS.64 fragments ----
        {
            const float* As = smf + AOF + (c&1)*ASTG + (mt*16 + g)*RS
                              + kh*32 + 2*tig;
            const float* Bs = smf + BOF + (c&1)*BSTG + g*RS + kh*32 + 2*tig;
            #pragma unroll
            for (int ks = 0; ks < 4; ++ks) {
                const int ko = ks*8;
                float2 aLo = *reinterpret_cast<const float2*>(As + ko);
                float2 aHi = *reinterpret_cast<const float2*>(As + 8*RS + ko);
                uint32_t a[4];
                a[0] = f2tf(aLo.x);
                a[1] = f2tf(aHi.x);
                a[2] = f2tf(aLo.y);
                a[3] = f2tf(aHi.y);
                #pragma unroll
                for (int j = 0; j < 5; ++j) {
                    float2 bb = *reinterpret_cast<const float2*>(
                        Bs + j*8*RS + ko);
                    uint32_t bf[2];
                    bf[0] = f2tf(bb.x);
                    bf[1] = f2tf(bb.y);
                    mma1688(acc[j], a, bf);
                }
            }
        }

        // ---- per-row sxx (overlaps MMA latency) ----
        if (t < 144) {
            const float* rp = smf + (srow < 36
                ? AOF + (c&1)*ASTG + srow*RS
                : BOF + (c&1)*BSTG + (srow-36)*RS) + shalf*32;
            #pragma unroll
            for (int j = 0; j < 8; ++j) {
                ulonglong2 v = *reinterpret_cast<const ulonglong2*>(rp + j*4);
                fma2(sxx2, v.x, v.x);
                fma2(sxx2, v.y, v.y);
            }
        }
    }

    if (t < 144) smf[STF + t] = lo32(sxx2) + hi32(sxx2);

    // ---- merge kh partials: kh1 -> smem scratch (B stage 0, dead) ----
    if (kh == 1) {
        float* sc = smf + XCF + mt*672 + lid*21;
        #pragma unroll
        for (int j = 0; j < 5; ++j)
            #pragma unroll
            for (int e = 0; e < 4; ++e) sc[j*4 + e] = acc[j][e];
    }
    __syncthreads();
    if (kh == 0) {
        const float* sc = smf + XCF + mt*672 + lid*21;
        #pragma unroll
        for (int j = 0; j < 5; ++j)
            #pragma unroll
            for (int e = 0; e < 4; ++e) acc[j][e] += sc[j*4 + e];

        // ---- extract MMA-computed stats: col36 = x.gw, col37 = sum(x),
        //      row36 = gw.y, row37 = sum(y), (36,37) = sum(gw) ----
        #pragma unroll
        for (int j = 0; j < 5; ++j) {
            int r0 = mt*16 + g;
            int c0 = j*8 + 2*tig;
            #pragma unroll
            for (int e = 0; e < 4; ++e) {
                int rr = r0 + (e >> 1)*8;
                int cc = c0 + (e & 1);
                float val = acc[j][e];
                if (rr < 36) {
                    if (cc == 36)      smf[SXGF + rr] = val;
                    else if (cc == 37) smf[SXF + rr] = val;
                } else if (rr == 36) {
                    if (cc < 36)       smf[SXGF + 36 + cc] = val;
                    else if (cc == 37) smf[SGWS] = val;
                } else if (rr == 37 && cc < 36) {
                    smf[SXF + 36 + cc] = val;
                }
            }
        }
    }
    __syncthreads();    // stage buffers fully dead -> aliases live

    // per-row finalize (72 rows)
    if (t < 72) {
        float Sxx = smf[STF + 2*t] + smf[STF + 2*t + 1];
        float Sx  = smf[SXF + t];
        float Sxg = smf[SXGF + t];
        float Sgw = smf[SGWS];
        float Sbw = 0.f;
        #pragma unroll
        for (int j = 0; j < 6; ++j) Sbw += smf[WPF + j];
        smf[RNF + t] = rsqrtf(Sxx);
        float mu  = Sx * (1.f/768.f);
        float var = Sxx * (1.f/768.f) - mu*mu;
        float rsd = rsqrtf(var + 1e-5f);
        smf[DUF + t] = tanhf((Sxg - mu*Sgw)*rsd + Sbw + Blin[0]) * 10.f;
    }
    if (t < 37) {
        smf[UF + t] = 0.f; smf[VF + t] = 0.f;
        smf[EUF + t] = 1.f; smf[EVF + t] = 1.f;
    }
    if (t == 0) smf[TOTF] = 0.f;
    __syncthreads();

    // write scaled couplings from merged accumulators (kh0 warps)
    if (kh == 0) {
        #pragma unroll
        for (int j = 0; j < 5; ++j) {
            int r0 = mt*16 + g;
            int c0 = j*8 + 2*tig;
            #pragma unroll
            for (int e = 0; e < 4; ++e) {
                int rr = r0 + (e >> 1)*8;
                int cc = c0 + (e & 1);
                if (rr < 36 && cc < 36)
                    smf[CSF + rr*37 + cc] =
                        acc[j][e] * smf[RNF+rr] * smf[RNF+36+cc] * 10.f;
            }
        }
    }
    if (t < 36) {
        smf[CSF + t*37 + 36] = smf[DUF + t];
        smf[CSF + 36*37 + t] = smf[DUF + 36 + t];
    }
    if (t == 0) smf[CSF + 36*37 + 36] = -1000.f;
    __syncthreads();

    for (int i = t; i < NP1; i += THREADS) smf[ECF + i] = __expf(smf[CSF + i]);
    __syncthreads();

    // ---- Sinkhorn: warps 0-1 only, named barrier ----
    if (t < 64) {
        const int m = t;
        const bool act = t < 37;
        const float lr = (m < 36) ? NORMC : LMD;
        #pragma unroll 1
        for (int it = 0; it < 20; ++it) {
            if (act) {
                const float* er = smf + ECF + m*37;
                float s0=0.f, s1=0.f, s2=0.f, s3=0.f;
                #pragma unroll
                for (int n = 0; n < 36; n += 4) {
                    s0 = fmaf(er[n+0], smf[EVF+n+0], s0);
                    s1 = fmaf(er[n+1], smf[EVF+n+1], s1);
                    s2 = fmaf(er[n+2], smf[EVF+n+2], s2);
                    s3 = fmaf(er[n+3], smf[EVF+n+3], s3);
                }
                s0 = fmaf(er[36], smf[EVF+36], s0);
                float uu = lr - __logf((s0+s1)+(s2+s3));
                smf[UF + m] = uu;
                smf[EUF + m] = __expf(uu);
            }
            asm volatile("bar.sync 5, 64;" ::: "memory");
            if (act) {
                const float* ecc = smf + ECF + m;
                float s0=0.f, s1=0.f, s2=0.f, s3=0.f;
                #pragma unroll
                for (int n = 0; n < 36; n += 4) {
                    s0 = fmaf(ecc[(n+0)*37], smf[EUF+n+0], s0);
                    s1 = fmaf(ecc[(n+1)*37], smf[EUF+n+1], s1);
                    s2 = fmaf(ecc[(n+2)*37], smf[EUF+n+2], s2);
                    s3 = fmaf(ecc[(n+3)*37], smf[EUF+n+3], s3);
                }
                s0 = fmaf(ecc[36*37], smf[EUF+36], s0);
                float vv = lr - __logf((s0+s1)+(s2+s3));
                smf[VF + m] = vv;
                smf[EVF + m] = __expf(vv);
            }
            asm volatile("bar.sync 5, 64;" ::: "memory");
        }
    }
    __syncthreads();

    // ---- epilogue: Z + total;  exp(Z) = 72 * ec * eu * ev ----
    float* ob = out + (size_t)b * NP1;
    float part = 0.f;
    for (int i = t; i < NP1; i += THREADS) {
        int mm = i / 37;
        int nn = i - mm*37;
        float cc = smf[CSF + i];
        ob[i] = cc + smf[UF + mm] + smf[VF + nn] - NORMC;
        if (mm < 36 && nn < 36)
            part += smf[ECF + i] * smf[EUF + mm] * smf[EVF + nn] * cc;
    }
    #pragma unroll
    for (int o = 16; o > 0; o >>= 1)
        part += __shfl_down_sync(0xffffffffu, part, o);
    if (lid == 0) atomicAdd(&smf[TOTF], part * 72.f);
    __syncthreads();
    if (t == 0) out[(size_t)B*NP1 + b] = smf[TOTF];
}

// ======================= launch =========================================
extern "C" void kernel_launch(void* const* d_in, const int* in_sizes, int n_in,
                              void* d_out, int out_size)
{
    const float* x  = (const float*)d_in[0];
    const float* y  = (const float*)d_in[1];
    const float* g  = (const float*)d_in[2];
    const float* bb = (const float*)d_in[3];
    const float* w  = (const float*)d_in[4];
    const float* bl = (const float*)d_in[5];
    const int B = in_sizes[0] / (36 * 768);
    float* out = (float*)d_out;

    cudaFuncSetAttribute(k_fused,
                         cudaFuncAttributeMaxDynamicSharedMemorySize, SM_BYTES);
    k_fused<<<B, THREADS, SM_BYTES>>>(x, y, g, bb, w, bl, out, B);
}